// round 7
// baseline (speedup 1.0000x reference)
#include <cuda_runtime.h>

// Spline1DInterpolant: out[q] = sum_i c[i] * u(|s_q + 2 - (i+1)|),
// s = (x - a)/h, h = (b - a)/n. Cubic B-spline, support t < 2 => exactly 4
// consecutive taps per query: i = floor(s) .. floor(s)+3.
//
// Latency/overhead-bound (one wave, all pipes <3%). Empirically best combo:
//  - vec4: 4 queries/thread, float4 x/out, 128 single-warp blocks (fewest
//    instructions + smallest grid footprint; bench-best shape).
//  - exactly ONE L2 prefetch line of c per block (128 total chip-wide covers
//    the whole 16KB table; overlaps the x DRAM latency so dependent gathers
//    hit L2). More prefetches (per-thread L1) measurably regress via L1tex
//    queue contention.

__device__ __forceinline__ float bspline_basis(float t) {
    // t in [0,2]; inner (t<=1): 4 - 6t^2 + 3t^3 ; outer: (2-t)^3
    float t2 = t * t;
    float inner = 4.0f - 6.0f * t2 + 3.0f * t2 * t;
    float om = 2.0f - t;
    float outer = om * om * om;
    return (t <= 1.0f) ? inner : outer;
}

__device__ __forceinline__ float eval_query(float xq, float a0, float h,
                                            const float* __restrict__ c, int nc) {
    float s = (xq - a0) / h;          // reference-exact formulation
    int i0 = (int)floorf(s);
    float sum = 0.0f;
#pragma unroll
    for (int k = 0; k < 4; k++) {
        int i = i0 + k;
        float t = fabsf(s + 2.0f - (float)(i + 1));   // same cancellation as ref
        float u = bspline_basis(t);
        if ((unsigned)i < (unsigned)nc) {
            sum = fmaf(__ldg(c + i), u, sum);
        }
    }
    return sum;
}

__global__ void __launch_bounds__(32)
spline1d_vec4(const float4* __restrict__ x4,
              const float* __restrict__ a,
              const float* __restrict__ b,
              const float* __restrict__ n,
              const float* __restrict__ c,
              float4* __restrict__ out4,
              int nb4, int nc) {
    // One L2 prefetch line per block, issued before anything x-dependent.
    // 128 blocks x 32 floats = 4096 coefficients covered exactly.
    if (threadIdx.x == 0) {
        int line = blockIdx.x * 32;
        if (line < nc)
            asm volatile("prefetch.global.L2 [%0];" :: "l"(c + line));
        // coverage for nc > gridDim.x*32 (not hit for this shape)
        for (int l = line + (int)gridDim.x * 32; l < nc; l += (int)gridDim.x * 32)
            asm volatile("prefetch.global.L2 [%0];" :: "l"(c + l));
    }

    int tid = blockIdx.x * 32 + threadIdx.x;
    if (tid >= nb4) return;

    // Independent loads issue together: x vector + broadcast scalars.
    float4 xv = __ldg(x4 + tid);
    float a0 = __ldg(a);
    float h  = (__ldg(b) - a0) / __ldg(n);

    float4 r;
    r.x = eval_query(xv.x, a0, h, c, nc);
    r.y = eval_query(xv.y, a0, h, c, nc);
    r.z = eval_query(xv.z, a0, h, c, nc);
    r.w = eval_query(xv.w, a0, h, c, nc);

    out4[tid] = r;
}

// Scalar tail (only if nb % 4 != 0; never for the fixed B=16384 shape).
__global__ void __launch_bounds__(32)
spline1d_tail(const float* __restrict__ x,
              const float* __restrict__ a,
              const float* __restrict__ b,
              const float* __restrict__ n,
              const float* __restrict__ c,
              float* __restrict__ out,
              int start, int nb, int nc) {
    int tid = start + blockIdx.x * 32 + threadIdx.x;
    if (tid >= nb) return;
    float a0 = __ldg(a);
    float h  = (__ldg(b) - a0) / __ldg(n);
    out[tid] = eval_query(__ldg(x + tid), a0, h, c, nc);
}

extern "C" void kernel_launch(void* const* d_in, const int* in_sizes, int n_in,
                              void* d_out, int out_size) {
    const float* x = (const float*)d_in[0];   // [B,1] fp32
    const float* a = (const float*)d_in[1];   // [1]
    const float* b = (const float*)d_in[2];   // [1]
    const float* n = (const float*)d_in[3];   // [1]
    const float* c = (const float*)d_in[4];   // [C]
    float* out = (float*)d_out;

    int nb = in_sizes[0];      // 16384
    int nc = in_sizes[4];      // 4096

    int nb4 = nb >> 2;
    if (nb4 > 0) {
        int blocks = (nb4 + 31) / 32;          // 128 single-warp blocks
        spline1d_vec4<<<blocks, 32>>>((const float4*)x, a, b, n, c,
                                      (float4*)out, nb4, nc);
    }
    int rem = nb & 3;
    if (rem) {
        spline1d_tail<<<1, 32>>>(x, a, b, n, c, out, nb4 << 2, nb, nc);
    }
}

// round 8
// speedup vs baseline: 1.0047x; 1.0047x over previous
#include <cuda_runtime.h>

// Spline1DInterpolant: out[q] = sum_i c[i] * u(|s_q + 2 - (i+1)|),
// s = (x - a)/h, h = (b - a)/n. Cubic B-spline, support t < 2 => exactly 4
// consecutive taps per query: i = floor(s) .. floor(s)+3.
//
// OVERHEAD-BOUND: warm kernel ~6000 cyc ~= T_ovh(5000) + one tiny CTA; all
// pipes <3%. Terminal shape: minimum grid (32 CTAs x 128 thr), minimum
// instruction count (vec4 ld/st, 4 queries/thread), single launch, one-shot
// 128-line L2 prefetch of c from block 0 (16KB table; overlaps x latency).

__device__ __forceinline__ float bspline_basis(float t) {
    // t in [0,2]; inner (t<=1): 4 - 6t^2 + 3t^3 ; outer: (2-t)^3
    float t2 = t * t;
    float inner = 4.0f - 6.0f * t2 + 3.0f * t2 * t;
    float om = 2.0f - t;
    float outer = om * om * om;
    return (t <= 1.0f) ? inner : outer;
}

__device__ __forceinline__ float eval_query(float xq, float a0, float h,
                                            const float* __restrict__ c, int nc) {
    float s = (xq - a0) / h;          // reference-exact formulation
    int i0 = (int)floorf(s);
    float sum = 0.0f;
#pragma unroll
    for (int k = 0; k < 4; k++) {
        int i = i0 + k;
        float t = fabsf(s + 2.0f - (float)(i + 1));   // same cancellation as ref
        float u = bspline_basis(t);
        if ((unsigned)i < (unsigned)nc) {
            sum = fmaf(__ldg(c + i), u, sum);
        }
    }
    return sum;
}

__global__ void __launch_bounds__(128)
spline1d_vec4(const float4* __restrict__ x4,
              const float* __restrict__ a,
              const float* __restrict__ b,
              const float* __restrict__ n,
              const float* __restrict__ c,
              float4* __restrict__ out4,
              int nb4, int nc) {
    // Block 0 prefetches the whole c table to (shared) L2: 128 threads x one
    // 128B line = 16KB. Non-blocking, independent of x, issued first.
    if (blockIdx.x == 0) {
        for (int line = threadIdx.x * 32; line < nc; line += 128 * 32) {
            asm volatile("prefetch.global.L2 [%0];" :: "l"(c + line));
        }
    }

    int tid = blockIdx.x * 128 + threadIdx.x;
    if (tid >= nb4) return;

    // Independent loads issue together: x vector + broadcast scalars.
    float4 xv = __ldg(x4 + tid);
    float a0 = __ldg(a);
    float h  = (__ldg(b) - a0) / __ldg(n);

    float4 r;
    r.x = eval_query(xv.x, a0, h, c, nc);
    r.y = eval_query(xv.y, a0, h, c, nc);
    r.z = eval_query(xv.z, a0, h, c, nc);
    r.w = eval_query(xv.w, a0, h, c, nc);

    out4[tid] = r;
}

// Scalar tail (only if nb % 4 != 0; never for the fixed B=16384 shape).
__global__ void __launch_bounds__(128)
spline1d_tail(const float* __restrict__ x,
              const float* __restrict__ a,
              const float* __restrict__ b,
              const float* __restrict__ n,
              const float* __restrict__ c,
              float* __restrict__ out,
              int start, int nb, int nc) {
    int tid = start + blockIdx.x * 128 + threadIdx.x;
    if (tid >= nb) return;
    float a0 = __ldg(a);
    float h  = (__ldg(b) - a0) / __ldg(n);
    out[tid] = eval_query(__ldg(x + tid), a0, h, c, nc);
}

extern "C" void kernel_launch(void* const* d_in, const int* in_sizes, int n_in,
                              void* d_out, int out_size) {
    const float* x = (const float*)d_in[0];   // [B,1] fp32
    const float* a = (const float*)d_in[1];   // [1]
    const float* b = (const float*)d_in[2];   // [1]
    const float* n = (const float*)d_in[3];   // [1]
    const float* c = (const float*)d_in[4];   // [C]
    float* out = (float*)d_out;

    int nb = in_sizes[0];      // 16384
    int nc = in_sizes[4];      // 4096

    int nb4 = nb >> 2;                         // 4096 threads
    if (nb4 > 0) {
        int blocks = (nb4 + 127) / 128;        // 32 CTAs of 128 threads
        spline1d_vec4<<<blocks, 128>>>((const float4*)x, a, b, n, c,
                                       (float4*)out, nb4, nc);
    }
    int rem = nb & 3;
    if (rem) {
        spline1d_tail<<<1, 128>>>(x, a, b, n, c, out, nb4 << 2, nb, nc);
    }
}

// round 12
// speedup vs baseline: 1.0746x; 1.0697x over previous
#include <cuda_runtime.h>

// Spline1DInterpolant: out[q] = sum_i c[i] * u(|s_q + 2 - (i+1)|),
// s = (x - a)/h, h = (b - a)/n. Cubic B-spline, support t < 2 => exactly 4
// consecutive taps per query: i = floor(s) .. floor(s)+3.
//
// OVERHEAD-BOUND on the warm timed path (all pipes <3%, DRAM 0.2%).
// Empirical finding across 7 rounds: every prefetch/smem-staging variant
// LOSES ~0.4us on the warm bench (c is already L2-resident across replays;
// prefetches are pure queue/issue overhead). Terminal shape = bench-best R2:
// vec4 queries/thread, 128 single-warp blocks, direct gathers, nothing else.

__device__ __forceinline__ float bspline_basis(float t) {
    // t in [0,2]; inner (t<=1): 4 - 6t^2 + 3t^3 ; outer: (2-t)^3
    float t2 = t * t;
    float inner = 4.0f - 6.0f * t2 + 3.0f * t2 * t;
    float om = 2.0f - t;
    float outer = om * om * om;
    return (t <= 1.0f) ? inner : outer;
}

__device__ __forceinline__ float eval_query(float xq, float a0, float h,
                                            const float* __restrict__ c, int nc) {
    float s = (xq - a0) / h;          // reference-exact formulation
    int i0 = (int)floorf(s);
    float sum = 0.0f;
#pragma unroll
    for (int k = 0; k < 4; k++) {
        int i = i0 + k;
        float t = fabsf(s + 2.0f - (float)(i + 1));   // same cancellation as ref
        float u = bspline_basis(t);
        if ((unsigned)i < (unsigned)nc) {
            sum = fmaf(__ldg(c + i), u, sum);
        }
    }
    return sum;
}

__global__ void __launch_bounds__(32)
spline1d_vec4(const float4* __restrict__ x4,
              const float* __restrict__ a,
              const float* __restrict__ b,
              const float* __restrict__ n,
              const float* __restrict__ c,
              float4* __restrict__ out4,
              int nb4, int nc) {
    int tid = blockIdx.x * 32 + threadIdx.x;
    if (tid >= nb4) return;

    // Independent loads issue together: x vector + broadcast scalars.
    float4 xv = __ldg(x4 + tid);
    float a0 = __ldg(a);
    float h  = (__ldg(b) - a0) / __ldg(n);

    float4 r;
    r.x = eval_query(xv.x, a0, h, c, nc);
    r.y = eval_query(xv.y, a0, h, c, nc);
    r.z = eval_query(xv.z, a0, h, c, nc);
    r.w = eval_query(xv.w, a0, h, c, nc);

    out4[tid] = r;
}

// Scalar tail (only launched if nb % 4 != 0; never for the fixed B=16384 shape).
__global__ void __launch_bounds__(32)
spline1d_tail(const float* __restrict__ x,
              const float* __restrict__ a,
              const float* __restrict__ b,
              const float* __restrict__ n,
              const float* __restrict__ c,
              float* __restrict__ out,
              int start, int nb, int nc) {
    int tid = start + blockIdx.x * 32 + threadIdx.x;
    if (tid >= nb) return;
    float a0 = __ldg(a);
    float h  = (__ldg(b) - a0) / __ldg(n);
    out[tid] = eval_query(__ldg(x + tid), a0, h, c, nc);
}

extern "C" void kernel_launch(void* const* d_in, const int* in_sizes, int n_in,
                              void* d_out, int out_size) {
    const float* x = (const float*)d_in[0];   // [B,1] fp32
    const float* a = (const float*)d_in[1];   // [1]
    const float* b = (const float*)d_in[2];   // [1]
    const float* n = (const float*)d_in[3];   // [1]
    const float* c = (const float*)d_in[4];   // [C]
    float* out = (float*)d_out;

    int nb = in_sizes[0];      // 16384
    int nc = in_sizes[4];      // 4096

    int nb4 = nb >> 2;
    if (nb4 > 0) {
        int blocks = (nb4 + 31) / 32;          // 128 single-warp blocks
        spline1d_vec4<<<blocks, 32>>>((const float4*)x, a, b, n, c,
                                      (float4*)out, nb4, nc);
    }
    int rem = nb & 3;
    if (rem) {
        spline1d_tail<<<1, 32>>>(x, a, b, n, c, out, nb4 << 2, nb, nc);
    }
}